// round 5
// baseline (speedup 1.0000x reference)
#include <cuda_runtime.h>
#include <cooperative_groups.h>
namespace cg = cooperative_groups;

#define FRAME_NUMBER 16
#define FRAME_SIZE   128
#define SAMPLE_NUM   16
#define NUM_EVENTS   1048576
#define EV_PER_FRAME (NUM_EVENTS / FRAME_NUMBER)      /* 65536 */
#define BINS         (FRAME_SIZE * FRAME_SIZE)        /* 16384 bins = 64 KB f32 */

// Scratch: packed bin id (y*128 + x) per event, u16 (bin < 16384). 2 MB.
__device__ unsigned short g_bins[NUM_EVENTS];

// ---------------------------------------------------------------------------
// Prepass: pack (x, y) -> u16 bin, handling int64 OR int32 index dtype.
// Detection: view buffer as int32. If dtype is int64, words [N-1],[N-3],... are
// HIGH words of mid-range sorted t values -> all zero. If int32, those words
// are the tail of the sorted t row (~65535) -> nonzero.
// ---------------------------------------------------------------------------
__global__ __launch_bounds__(256)
void bins_kernel(const int* __restrict__ idx32) {
    const int e = (blockIdx.x * blockDim.x + threadIdx.x) * 4;  // first event
    const bool is64 = (idx32[NUM_EVENTS - 1] == 0) &&
                      (idx32[NUM_EVENTS - 3] == 0) &&
                      (idx32[NUM_EVENTS - 5] == 0) &&
                      (idx32[NUM_EVENTS - 7] == 0);
    int x0, x1, x2, x3, y0, y1, y2, y3;
    if (is64) {
        const longlong2* __restrict__ px =
            reinterpret_cast<const longlong2*>(idx32) + (NUM_EVENTS + e) / 2;
        const longlong2* __restrict__ py =
            reinterpret_cast<const longlong2*>(idx32) + (2 * NUM_EVENTS + e) / 2;
        longlong2 xa = px[0], xb = px[1];
        longlong2 ya = py[0], yb = py[1];
        x0 = (int)xa.x; x1 = (int)xa.y; x2 = (int)xb.x; x3 = (int)xb.y;
        y0 = (int)ya.x; y1 = (int)ya.y; y2 = (int)yb.x; y3 = (int)yb.y;
    } else {
        const int4 x4 = *reinterpret_cast<const int4*>(idx32 + NUM_EVENTS + e);
        const int4 y4 = *reinterpret_cast<const int4*>(idx32 + 2 * NUM_EVENTS + e);
        x0 = x4.x; x1 = x4.y; x2 = x4.z; x3 = x4.w;
        y0 = y4.x; y1 = y4.y; y2 = y4.z; y3 = y4.w;
    }
    ushort4 o;
    o.x = (unsigned short)(y0 * FRAME_SIZE + x0);
    o.y = (unsigned short)(y1 * FRAME_SIZE + x1);
    o.z = (unsigned short)(y2 * FRAME_SIZE + x2);
    o.w = (unsigned short)(y3 * FRAME_SIZE + x3);
    *reinterpret_cast<ushort4*>(g_bins + e) = o;
}

// ---------------------------------------------------------------------------
// Main: cluster of 2 CTAs per (frame, sample) — distributed histogram.
// CTA rank r (= blockIdx.z) owns channel r's 128x128 f32 hist (64 KB smem ->
// 2 CTAs/SM, 64 warps feeding the ATOMS pipe). Each CTA processes HALF the
// frame's events; every event issues exactly ONE atomicAdd of |v| to the
// channel-owning CTA's hist — local or peer via DSMEM (map_shared_rank).
// out[f, s, c, y, x] : flat = ((f*S + s)*2 + c)*16384 + y*128 + x
// ---------------------------------------------------------------------------
#define TPB      1024
#define EV_PER_T 4                          /* events per thread per chunk */
#define HALF_EV  (EV_PER_FRAME / 2)         /* 32768 events per CTA */
#define CHUNK    (TPB * EV_PER_T)           /* 4096 */
#define NITER    (HALF_EV / CHUNK)          /* 8 */

__global__ void __cluster_dims__(1, 1, 2) __launch_bounds__(TPB, 2)
accum_kernel(const float* __restrict__ vals, float* __restrict__ out) {
    extern __shared__ float hist[];         // BINS floats = 64 KB (own channel)
    const int f = blockIdx.x;
    const int s = blockIdx.y;
    const unsigned rank = blockIdx.z;       // cluster rank: 0 = neg ch, 1 = pos ch

    cg::cluster_group cluster = cg::this_cluster();
    float* peer = cluster.map_shared_rank(hist, rank ^ 1u);
    float* const pos_base = rank ? hist : peer;   // channel-1 hist
    float* const neg_base = rank ? peer : hist;   // channel-0 hist

    // zero own hist
    {
        float4 z = make_float4(0.f, 0.f, 0.f, 0.f);
        float4* h4 = reinterpret_cast<float4*>(hist);
        #pragma unroll
        for (int i = threadIdx.x; i < BINS / 4; i += TPB) h4[i] = z;
    }
    cluster.sync();   // peers may atomically target my hist from here on

    const float* __restrict__ v = vals + (size_t)s * NUM_EVENTS
                                       + (size_t)f * EV_PER_FRAME + rank * HALF_EV;
    const unsigned short* __restrict__ b =
        g_bins + f * EV_PER_FRAME + rank * HALF_EV;

    const int t4 = threadIdx.x * EV_PER_T;

    // double-buffered (lean: fits 32 regs at occupancy 2)
    float4 cv = *reinterpret_cast<const float4*>(v + t4);
    uint2  cb = *reinterpret_cast<const uint2*>(b + t4);

    #pragma unroll
    for (int it = 0; it < NITER; ++it) {
        float4 nv; uint2 nb;
        if (it + 1 < NITER) {
            const int idx = (it + 1) * CHUNK + t4;
            nv = *reinterpret_cast<const float4*>(v + idx);
            nb = *reinterpret_cast<const uint2*>(b + idx);
        }
        atomicAdd((cv.x > 0.0f ? pos_base : neg_base) + (cb.x & 0xFFFFu), fabsf(cv.x));
        atomicAdd((cv.y > 0.0f ? pos_base : neg_base) + (cb.x >> 16),     fabsf(cv.y));
        atomicAdd((cv.z > 0.0f ? pos_base : neg_base) + (cb.y & 0xFFFFu), fabsf(cv.z));
        atomicAdd((cv.w > 0.0f ? pos_base : neg_base) + (cb.y >> 16),     fabsf(cv.w));
        if (it + 1 < NITER) { cv = nv; cb = nb; }
    }

    cluster.sync();   // all atomics (incl. peer's into my hist) complete & visible

    // coalesced writeback of own channel
    float4* __restrict__ o = reinterpret_cast<float4*>(
        out + ((size_t)(f * SAMPLE_NUM + s) * 2 + rank) * BINS);
    const float4* h4 = reinterpret_cast<const float4*>(hist);
    #pragma unroll
    for (int i = threadIdx.x; i < BINS / 4; i += TPB) o[i] = h4[i];
}

extern "C" void kernel_launch(void* const* d_in, const int* in_sizes, int n_in,
                              void* d_out, int out_size) {
    (void)in_sizes; (void)n_in; (void)out_size;
    const float* vals  = (const float*)d_in[0];
    const int*   idx32 = (const int*)d_in[1];   // raw view; dtype detected on device
    float*       out   = (float*)d_out;

    cudaFuncSetAttribute(accum_kernel,
                         cudaFuncAttributeMaxDynamicSharedMemorySize,
                         BINS * (int)sizeof(float));

    bins_kernel<<<NUM_EVENTS / (256 * 4), 256>>>(idx32);
    accum_kernel<<<dim3(FRAME_NUMBER, SAMPLE_NUM, 2), TPB,
                   BINS * sizeof(float)>>>(vals, out);
}

// round 6
// speedup vs baseline: 3.7307x; 3.7307x over previous
#include <cuda_runtime.h>

#define FRAME_NUMBER 16
#define FRAME_SIZE   128
#define SAMPLE_NUM   16
#define NUM_EVENTS   1048576
#define EV_PER_FRAME (NUM_EVENTS / FRAME_NUMBER)      /* 65536 */
#define BINS         (FRAME_SIZE * FRAME_SIZE)        /* 16384 bins = 64 KB f32 */

// Scratch: packed bin id (y*128 + x) per event, u16 (bin < 16384). 2 MB.
__device__ unsigned short g_bins[NUM_EVENTS];

// ---------------------------------------------------------------------------
// Prepass: pack (x, y) -> u16 bin, handling int64 OR int32 index dtype.
// Detection: view buffer as int32. If dtype is int64, words [N-1],[N-3],... are
// HIGH words of mid-range sorted t values -> all zero. If int32, those words
// are the tail of the sorted t row (~65535) -> nonzero.
// ---------------------------------------------------------------------------
__global__ __launch_bounds__(256)
void bins_kernel(const int* __restrict__ idx32) {
    const int e = (blockIdx.x * blockDim.x + threadIdx.x) * 4;  // first event
    const bool is64 = (idx32[NUM_EVENTS - 1] == 0) &&
                      (idx32[NUM_EVENTS - 3] == 0) &&
                      (idx32[NUM_EVENTS - 5] == 0) &&
                      (idx32[NUM_EVENTS - 7] == 0);
    int x0, x1, x2, x3, y0, y1, y2, y3;
    if (is64) {
        const longlong2* __restrict__ px =
            reinterpret_cast<const longlong2*>(idx32) + (NUM_EVENTS + e) / 2;
        const longlong2* __restrict__ py =
            reinterpret_cast<const longlong2*>(idx32) + (2 * NUM_EVENTS + e) / 2;
        longlong2 xa = px[0], xb = px[1];
        longlong2 ya = py[0], yb = py[1];
        x0 = (int)xa.x; x1 = (int)xa.y; x2 = (int)xb.x; x3 = (int)xb.y;
        y0 = (int)ya.x; y1 = (int)ya.y; y2 = (int)yb.x; y3 = (int)yb.y;
    } else {
        const int4 x4 = *reinterpret_cast<const int4*>(idx32 + NUM_EVENTS + e);
        const int4 y4 = *reinterpret_cast<const int4*>(idx32 + 2 * NUM_EVENTS + e);
        x0 = x4.x; x1 = x4.y; x2 = x4.z; x3 = x4.w;
        y0 = y4.x; y1 = y4.y; y2 = y4.z; y3 = y4.w;
    }
    ushort4 o;
    o.x = (unsigned short)(y0 * FRAME_SIZE + x0);
    o.y = (unsigned short)(y1 * FRAME_SIZE + x1);
    o.z = (unsigned short)(y2 * FRAME_SIZE + x2);
    o.w = (unsigned short)(y3 * FRAME_SIZE + x3);
    *reinterpret_cast<ushort4*>(g_bins + e) = o;
}

// ---------------------------------------------------------------------------
// Main: one CTA per (channel, frame, sample). 64 KB single-channel hist ->
// 2 CTAs/SM, 64 warps feeding the ATOMS pipe. Each CTA reads ALL events of
// its (f,s); sign-matching events are COMPACTED into full warps via a
// per-warp 64-entry smem ring queue (ballot + prefix rank), so every ATOMS
// instruction has 32 active lanes (fixes round-3's predicated-lane waste).
// Channel pairs adjacent in grid-x -> second value read hits L2.
// out[f, s, c, y, x] : flat = ((f*S + s)*2 + c)*16384 + y*128 + x
// ---------------------------------------------------------------------------
#define TPB      1024
#define EV_PER_T 4
#define CHUNK    (TPB * EV_PER_T)           /* 4096 */
#define NITER    (EV_PER_FRAME / CHUNK)     /* 16 */
#define NWARP    (TPB / 32)                 /* 32 */
#define CAP      64                         /* ring capacity per warp */
/* dynamic smem: hist[BINS] f32 + qbin[NWARP*CAP] u32 + qval[NWARP*CAP] f32 */
#define SMEM_BYTES (BINS * 4 + NWARP * CAP * 8)   /* 80 KB */

__global__ __launch_bounds__(TPB, 2)
void accum_kernel(const float* __restrict__ vals, float* __restrict__ out) {
    extern __shared__ float smem[];
    float*    hist   = smem;
    unsigned* qb_all = reinterpret_cast<unsigned*>(smem + BINS);
    float*    qv_all = reinterpret_cast<float*>(qb_all + NWARP * CAP);

    const int c = blockIdx.x;               // channel: 0 = neg, 1 = pos
    const int f = blockIdx.y;
    const int s = blockIdx.z;
    const float sgn = c ? 1.0f : -1.0f;

    const int wid  = threadIdx.x >> 5;
    const int lane = threadIdx.x & 31;
    unsigned* __restrict__ qb = qb_all + wid * CAP;
    float*    __restrict__ qv = qv_all + wid * CAP;
    const unsigned lmask = (1u << lane) - 1u;

    // zero hist
    {
        float4 z = make_float4(0.f, 0.f, 0.f, 0.f);
        float4* h4 = reinterpret_cast<float4*>(hist);
        #pragma unroll
        for (int i = threadIdx.x; i < BINS / 4; i += TPB) h4[i] = z;
    }
    __syncthreads();

    const float* __restrict__ v =
        vals + (size_t)s * NUM_EVENTS + (size_t)f * EV_PER_FRAME;
    const unsigned short* __restrict__ b = g_bins + f * EV_PER_FRAME;
    const int t4 = threadIdx.x * EV_PER_T;

    int qn = 0, qd = 0;   // warp-uniform enqueue / drain counters

    float4 cv = *reinterpret_cast<const float4*>(v + t4);
    uint2  cb = *reinterpret_cast<const uint2*>(b + t4);

    #pragma unroll 2
    for (int it = 0; it < NITER; ++it) {
        float4 nv; uint2 nb;
        if (it + 1 < NITER) {
            const int idx = (it + 1) * CHUNK + t4;
            nv = *reinterpret_cast<const float4*>(v + idx);
            nb = *reinterpret_cast<const uint2*>(b + idx);
        }

        #pragma unroll
        for (int j = 0; j < 4; ++j) {
            const float raw = (j == 0) ? cv.x : (j == 1) ? cv.y : (j == 2) ? cv.z : cv.w;
            const unsigned bin =
                (j == 0) ? (cb.x & 0xFFFFu) : (j == 1) ? (cb.x >> 16)
              : (j == 2) ? (cb.y & 0xFFFFu) : (cb.y >> 16);
            const float w = raw * sgn;
            const unsigned m = __ballot_sync(0xFFFFFFFFu, w > 0.0f);
            if (w > 0.0f) {                 // compact append at rank
                const int pos = (qn + __popc(m & lmask)) & (CAP - 1);
                qb[pos] = bin;
                qv[pos] = w;
            }
            qn += __popc(m);
            __syncwarp();                   // appends visible warp-wide
            if (qn - qd >= 32) {            // drain one FULL warp's worth
                const int idx = (qd + lane) & (CAP - 1);
                atomicAdd(&hist[qb[idx]], qv[idx]);
                qd += 32;
                __syncwarp();               // drain reads done before reuse
            }
        }

        if (it + 1 < NITER) { cv = nv; cb = nb; }
    }

    // final partial drain (< 32 entries)
    __syncwarp();
    {
        const int rem = qn - qd;
        if (lane < rem) {
            const int idx = (qd + lane) & (CAP - 1);
            atomicAdd(&hist[qb[idx]], qv[idx]);
        }
    }
    __syncthreads();

    // coalesced writeback of own channel
    float4* __restrict__ o = reinterpret_cast<float4*>(
        out + ((size_t)(f * SAMPLE_NUM + s) * 2 + c) * BINS);
    const float4* h4 = reinterpret_cast<const float4*>(hist);
    #pragma unroll
    for (int i = threadIdx.x; i < BINS / 4; i += TPB) o[i] = h4[i];
}

extern "C" void kernel_launch(void* const* d_in, const int* in_sizes, int n_in,
                              void* d_out, int out_size) {
    (void)in_sizes; (void)n_in; (void)out_size;
    const float* vals  = (const float*)d_in[0];
    const int*   idx32 = (const int*)d_in[1];   // raw view; dtype detected on device
    float*       out   = (float*)d_out;

    cudaFuncSetAttribute(accum_kernel,
                         cudaFuncAttributeMaxDynamicSharedMemorySize, SMEM_BYTES);

    bins_kernel<<<NUM_EVENTS / (256 * 4), 256>>>(idx32);
    accum_kernel<<<dim3(2, FRAME_NUMBER, SAMPLE_NUM), TPB, SMEM_BYTES>>>(vals, out);
}